// round 13
// baseline (speedup 1.0000x reference)
#include <cuda_runtime.h>
#include <cuda_fp16.h>
#include <cstdint>

#define H 4096
#define INF 4096
#define OUTF 4096
#define KRED 256
#define NRED 16

__device__ __half g_xs[H * KRED];
__device__ __half g_wsT[OUTF * KRED];
__device__ uint32_t g_cnt[64];   // [0..31] xs blocks, [32..63] wsT blocks
__device__ uint32_t g_rdq;       // reduce-unit dispenser
__device__ uint32_t g_gtq;       // gemm-tile dispenser

#define NRUNITS 2048
#define NTILES 1024

#define BM 128
#define BN 128
#define KC 64
#define LDSTR 72
#define A_BUF (BM * LDSTR)
#define B_BUF (BN * LDSTR)
#define STAGE_H (A_BUF + B_BUF)
#define STAGE_B (STAGE_H * 2)
#define SMEM_BYTES (3 * STAGE_B + 1024)   // 111616 B -> 2 CTAs/SM

__device__ __forceinline__ float4 ldcs4(const float4* p) {
    float4 v;
    asm volatile("ld.global.cs.v4.f32 {%0,%1,%2,%3}, [%4];"
                 : "=f"(v.x), "=f"(v.y), "=f"(v.z), "=f"(v.w) : "l"(p));
    return v;
}
__device__ __forceinline__ uint32_t ld_acq(const uint32_t* p) {
    uint32_t v;
    asm volatile("ld.acquire.gpu.global.u32 %0, [%1];" : "=r"(v) : "l"(p));
    return v;
}
__device__ __forceinline__ void red_release(uint32_t* p) {
    asm volatile("red.release.gpu.global.add.u32 [%0], 1;" :: "l"(p) : "memory");
}
__device__ __forceinline__ void mma_f16(float* d, const uint32_t* a, const uint32_t* b) {
    asm volatile(
        "mma.sync.aligned.m16n8k16.row.col.f32.f16.f16.f32 "
        "{%0,%1,%2,%3}, {%4,%5,%6,%7}, {%8,%9}, {%0,%1,%2,%3};\n"
        : "+f"(d[0]), "+f"(d[1]), "+f"(d[2]), "+f"(d[3])
        : "r"(a[0]), "r"(a[1]), "r"(a[2]), "r"(a[3]),
          "r"(b[0]), "r"(b[1]));
}
__device__ __forceinline__ void cp16(uint32_t dst, const void* src) {
    asm volatile("cp.async.cg.shared.global [%0], [%1], 16;"
                 :: "r"(dst), "l"(src) : "memory");
}
__device__ __forceinline__ void ldm_x4(uint32_t& r0, uint32_t& r1, uint32_t& r2,
                                       uint32_t& r3, uint32_t addr) {
    asm volatile("ldmatrix.sync.aligned.m8n8.x4.shared.b16 {%0,%1,%2,%3}, [%4];"
                 : "=r"(r0), "=r"(r1), "=r"(r2), "=r"(r3) : "r"(addr));
}

__global__ void __launch_bounds__(256, 2)
lin_coop(const float* __restrict__ x, const float* __restrict__ w,
         const float* __restrict__ bias, float* __restrict__ out) {
    extern __shared__ __half smh[];
    float* s_bias = (float*)(smh + 3 * STAGE_H);
    volatile int* s_idx = (volatile int*)(s_bias + 128);

    const int tid = threadIdx.x;
    const int warp = tid >> 5;
    const int lane = tid & 31;
    const bool gemmFirst = (blockIdx.x < (gridDim.x >> 1));

    // ---------------- phase A: reduction (half the CTAs) ----------------
    if (!gemmFirst) {
        const int rrow = tid >> 6;          // 0..3
        const int p = (tid & 63) * 4;
        for (;;) {
            if (tid == 0) *s_idx = (int)atomicAdd(&g_rdq, 1u);
            __syncthreads();
            const int u = *s_idx;
            if (u >= NRUNITS) break;

            const bool isW = u & 1;
            const int pair = u >> 1;
            const float* src = isW ? w : x;
            __half* dst = isW ? g_wsT : g_xs;
            const int row = pair * 4 + rrow;
            const float4* s = (const float4*)(src + (size_t)row * INF + p);
            float4 a0 = make_float4(0.f, 0.f, 0.f, 0.f);
            float4 a1 = make_float4(0.f, 0.f, 0.f, 0.f);
#pragma unroll
            for (int v = 0; v < NRED; v += 2) {
                float4 t0 = ldcs4(s + v * (KRED / 4));
                float4 t1 = ldcs4(s + (v + 1) * (KRED / 4));
                a0.x += t0.x; a0.y += t0.y; a0.z += t0.z; a0.w += t0.w;
                a1.x += t1.x; a1.y += t1.y; a1.z += t1.z; a1.w += t1.w;
            }
            a0.x += a1.x; a0.y += a1.y; a0.z += a1.z; a0.w += a1.w;
            __half2 lo = __floats2half2_rn(a0.x, a0.y);
            __half2 hi = __floats2half2_rn(a0.z, a0.w);
            uint2 pk = make_uint2(*(uint32_t*)&lo, *(uint32_t*)&hi);
            *(uint2*)(dst + (size_t)row * KRED + p) = pk;

            __threadfence();
            __syncthreads();
            if (tid == 0)
                red_release(&g_cnt[(isW ? 32 : 0) + (pair >> 5)]);
        }
    }

    // ---------------- phase B: GEMM tiles ----------------
    const int wm = warp >> 1;
    const int wn = warp & 1;
    const int g = lane >> 2;
    const int t = lane & 3;
    const int lrow = tid >> 3;
    const int lch = (tid & 7) * 8;

    const uint32_t smem0 = (uint32_t)__cvta_generic_to_shared(smh);
    const uint32_t aDst0 = smem0 + (lrow * LDSTR + lch) * 2;
    const uint32_t bDst0 = smem0 + (A_BUF + lrow * LDSTR + lch) * 2;

    const int aRow = (lane & 7) + ((lane >> 3) & 1) * 8;
    const int aK = (lane >> 4) * 8;
    const uint32_t aLdmOff = ((wm * 32 + aRow) * LDSTR + aK) * 2;
    const int bRow = (lane & 7) + ((lane >> 4) & 1) * 8;
    const int bK = ((lane >> 3) & 1) * 8;
    const uint32_t bLdmOff = (uint32_t)(A_BUF * 2) + ((wn * 64 + bRow) * LDSTR + bK) * 2;

    for (;;) {
        if (tid == 0) *s_idx = (int)atomicAdd(&g_gtq, 1u);
        __syncthreads();
        const int ti = *s_idx;
        if (ti >= NTILES) {
            // last exit ticket (one per CTA) -> safe global reset for graph replay
            if (tid == 0 && ti == NTILES + (int)gridDim.x - 1) {
#pragma unroll
                for (int i = 0; i < 64; i++) g_cnt[i] = 0;
                g_rdq = 0;
                __threadfence();
                g_gtq = 0;
            }
            break;
        }

        // shell mapping: tiles ordered by max(mb, nb) ascending
        int sh = (int)sqrtf((float)ti);
        while ((sh + 1) * (sh + 1) <= ti) sh++;
        while (sh * sh > ti) sh--;
        const int rsh = ti - sh * sh;
        const int mb = (rsh <= sh) ? rsh : sh;
        const int nb = (rsh <= sh) ? sh : (rsh - sh - 1);
        const int m0 = mb * BM;
        const int n0 = nb * BN;

        if (tid == 0) {
            while (ld_acq(&g_cnt[mb]) < 32u) __nanosleep(32);
            while (ld_acq(&g_cnt[32 + nb]) < 32u) __nanosleep(32);
        }
        if (tid < 128) s_bias[tid] = bias[n0 + tid];
        __syncthreads();

        const __half* aSrc = g_xs + (size_t)(m0 + lrow) * KRED + lch;
        const __half* bSrc = g_wsT + (size_t)(n0 + lrow) * KRED + lch;

        float acc[2][8][4];
#pragma unroll
        for (int mt = 0; mt < 2; mt++)
#pragma unroll
            for (int nt = 0; nt < 8; nt++)
#pragma unroll
                for (int i = 0; i < 4; i++) acc[mt][nt][i] = 0.f;

#pragma unroll
        for (int pc = 0; pc < 2; pc++) {
            const uint32_t so = pc * STAGE_B;
            const int kc = pc * KC;
#pragma unroll
            for (int r = 0; r < 4; r++) {
                cp16(aDst0 + so + r * 32 * LDSTR * 2, aSrc + (size_t)r * 32 * KRED + kc);
                cp16(bDst0 + so + r * 32 * LDSTR * 2, bSrc + (size_t)r * 32 * KRED + kc);
            }
            asm volatile("cp.async.commit_group;" ::: "memory");
        }

#pragma unroll
        for (int c = 0; c < 4; c++) {
            if (c < 3) asm volatile("cp.async.wait_group 1;" ::: "memory");
            else       asm volatile("cp.async.wait_group 0;" ::: "memory");
            __syncthreads();

            if (c < 2) {
                const int ns = (c + 2) % 3;
                const uint32_t so = ns * STAGE_B;
                const int kc = (c + 2) * KC;
#pragma unroll
                for (int r = 0; r < 4; r++) {
                    cp16(aDst0 + so + r * 32 * LDSTR * 2, aSrc + (size_t)r * 32 * KRED + kc);
                    cp16(bDst0 + so + r * 32 * LDSTR * 2, bSrc + (size_t)r * 32 * KRED + kc);
                }
                asm volatile("cp.async.commit_group;" ::: "memory");
            }

            const uint32_t stageBase = smem0 + (c % 3) * STAGE_B;
            const uint32_t aAddr = stageBase + aLdmOff;
            const uint32_t bAddr = stageBase + bLdmOff;

            uint32_t a[2][2][4], b[2][8][2];
#pragma unroll
            for (int mt = 0; mt < 2; mt++)
                ldm_x4(a[0][mt][0], a[0][mt][1], a[0][mt][2], a[0][mt][3],
                       aAddr + mt * 16 * LDSTR * 2);
#pragma unroll
            for (int np = 0; np < 4; np++)
                ldm_x4(b[0][2 * np][0], b[0][2 * np][1],
                       b[0][2 * np + 1][0], b[0][2 * np + 1][1],
                       bAddr + np * 16 * LDSTR * 2);

#pragma unroll
            for (int s = 0; s < 4; s++) {
                const int cur = s & 1;
                if (s < 3) {
                    const int nxt = cur ^ 1;
                    const int kkB = (s + 1) * 16 * 2;
#pragma unroll
                    for (int mt = 0; mt < 2; mt++)
                        ldm_x4(a[nxt][mt][0], a[nxt][mt][1], a[nxt][mt][2], a[nxt][mt][3],
                               aAddr + mt * 16 * LDSTR * 2 + kkB);
#pragma unroll
                    for (int np = 0; np < 4; np++)
                        ldm_x4(b[nxt][2 * np][0], b[nxt][2 * np][1],
                               b[nxt][2 * np + 1][0], b[nxt][2 * np + 1][1],
                               bAddr + np * 16 * LDSTR * 2 + kkB);
                }
#pragma unroll
                for (int mt = 0; mt < 2; mt++)
#pragma unroll
                    for (int nt = 0; nt < 8; nt++)
                        mma_f16(acc[mt][nt], a[cur][mt], b[cur][nt]);
            }
        }

#pragma unroll
        for (int mt = 0; mt < 2; mt++) {
            const int r0 = m0 + wm * 32 + mt * 16 + g;
#pragma unroll
            for (int nt = 0; nt < 8; nt++) {
                const int col = wn * 64 + nt * 8 + 2 * t;
                const float b0 = s_bias[col], b1 = s_bias[col + 1];
                float2 v0 = make_float2(acc[mt][nt][0] + b0, acc[mt][nt][1] + b1);
                float2 v1 = make_float2(acc[mt][nt][2] + b0, acc[mt][nt][3] + b1);
                *(float2*)&out[(size_t)r0 * OUTF + n0 + col] = v0;
                *(float2*)&out[(size_t)(r0 + 8) * OUTF + n0 + col] = v1;
            }
        }
        __syncthreads();
    }
}

extern "C" void kernel_launch(void* const* d_in, const int* in_sizes, int n_in,
                              void* d_out, int out_size) {
    const float* x = (const float*)d_in[0];
    const float* w = (const float*)d_in[1];
    const float* bias = (const float*)d_in[2];
    float* out = (float*)d_out;

    static int nsm = 0;
    if (nsm == 0) {
        int dev = 0;
        cudaGetDevice(&dev);
        cudaDeviceGetAttribute(&nsm, cudaDevAttrMultiProcessorCount, dev);
        cudaFuncSetAttribute(lin_coop, cudaFuncAttributeMaxDynamicSharedMemorySize, SMEM_BYTES);
    }

    lin_coop<<<2 * nsm, 256, SMEM_BYTES>>>(x, w, bias, out);
}

// round 14
// speedup vs baseline: 1.2742x; 1.2742x over previous
#include <cuda_runtime.h>
#include <cuda_fp16.h>
#include <cstdint>

#define H 4096
#define INF 4096
#define OUTF 4096
#define KRED 256
#define NRED 16

// Reduced operands in fp16. 2 MB each -> L2-resident through the GEMM.
__device__ __half g_xs[H * KRED];
__device__ __half g_wsT[OUTF * KRED];

// ---------------------------------------------------------------------------
// Fused reduction. Inputs streamed with evict-first (.cs).
// ---------------------------------------------------------------------------
__device__ __forceinline__ float4 ldcs4(const float4* p) {
    float4 v;
    asm volatile("ld.global.cs.v4.f32 {%0,%1,%2,%3}, [%4];"
                 : "=f"(v.x), "=f"(v.y), "=f"(v.z), "=f"(v.w) : "l"(p));
    return v;
}

__global__ void __launch_bounds__(256) lin_reduce(const float* __restrict__ x,
                                                  const float* __restrict__ w) {
    int b = blockIdx.x;
    const float* src;
    __half* dst;
    if (b < 1024) { src = x; dst = g_xs; }
    else          { src = w; dst = g_wsT; b -= 1024; }
    const int row = b * 4 + (threadIdx.x >> 6);
    const int p = (threadIdx.x & 63) * 4;
    const float4* s = (const float4*)(src + (size_t)row * INF + p);
    float4 a0 = make_float4(0.f, 0.f, 0.f, 0.f);
    float4 a1 = make_float4(0.f, 0.f, 0.f, 0.f);
#pragma unroll
    for (int v = 0; v < NRED; v += 2) {
        float4 t0 = ldcs4(s + v * (KRED / 4));
        float4 t1 = ldcs4(s + (v + 1) * (KRED / 4));
        a0.x += t0.x; a0.y += t0.y; a0.z += t0.z; a0.w += t0.w;
        a1.x += t1.x; a1.y += t1.y; a1.z += t1.z; a1.w += t1.w;
    }
    a0.x += a1.x; a0.y += a1.y; a0.z += a1.z; a0.w += a1.w;
    __half2 lo = __floats2half2_rn(a0.x, a0.y);
    __half2 hi = __floats2half2_rn(a0.z, a0.w);
    uint2 pk = make_uint2(*(uint32_t*)&lo, *(uint32_t*)&hi);
    *(uint2*)(dst + (size_t)row * KRED + p) = pk;
}

// ---------------------------------------------------------------------------
// GEMM via mma.sync fp16 + ldmatrix: out = xs @ wsT^T + bias
// CTA 128x128; 128 threads, 4 warps in 2x2 grid; warp tile 64x64.
// KC=64, 4 chunks, 3-stage cp.async pipeline. 2 CTAs per SM.
// ---------------------------------------------------------------------------
#define BM 128
#define BN 128
#define KC 64
#define LDSTR 72
#define A_BUF (BM * LDSTR)
#define B_BUF (BN * LDSTR)
#define STAGE_H (A_BUF + B_BUF)
#define STAGE_B (STAGE_H * 2)
#define SMEM_BYTES (3 * STAGE_B + 512)  // 111104 B -> 2 CTAs/SM

__device__ __forceinline__ void mma_f16(float* d, const uint32_t* a, const uint32_t* b) {
    asm volatile(
        "mma.sync.aligned.m16n8k16.row.col.f32.f16.f16.f32 "
        "{%0,%1,%2,%3}, {%4,%5,%6,%7}, {%8,%9}, {%0,%1,%2,%3};\n"
        : "+f"(d[0]), "+f"(d[1]), "+f"(d[2]), "+f"(d[3])
        : "r"(a[0]), "r"(a[1]), "r"(a[2]), "r"(a[3]),
          "r"(b[0]), "r"(b[1]));
}

__device__ __forceinline__ void cp16(uint32_t dst, const void* src) {
    asm volatile("cp.async.cg.shared.global [%0], [%1], 16;"
                 :: "r"(dst), "l"(src) : "memory");
}

__device__ __forceinline__ void ldm_x4(uint32_t& r0, uint32_t& r1, uint32_t& r2,
                                       uint32_t& r3, uint32_t addr) {
    asm volatile("ldmatrix.sync.aligned.m8n8.x4.shared.b16 {%0,%1,%2,%3}, [%4];"
                 : "=r"(r0), "=r"(r1), "=r"(r2), "=r"(r3) : "r"(addr));
}

__global__ void __launch_bounds__(128, 2)
lin_gemm(const float* __restrict__ bias, float* __restrict__ out) {
    extern __shared__ __half smh[];
    float* s_bias = (float*)(smh + 3 * STAGE_H);

    const int tid = threadIdx.x;
    const int warp = tid >> 5;
    const int lane = tid & 31;
    const int wm = warp >> 1;            // 0..1 -> 64-row slab
    const int wn = warp & 1;             // 0..1 -> 64-col slab
    const int g = lane >> 2;
    const int t = lane & 3;
    const int m0 = blockIdx.y * BM;
    const int n0 = blockIdx.x * BN;

    s_bias[tid] = bias[n0 + tid];        // 128 threads cover 128 cols

    // cooperative load: 16 base rows x 8 float4 cols, 8 row-passes
    const int lrow = tid >> 3;           // 0..15
    const int lch = (tid & 7) * 8;

    const uint32_t smem0 = (uint32_t)__cvta_generic_to_shared(smh);
    const uint32_t aDst0 = smem0 + (lrow * LDSTR + lch) * 2;
    const uint32_t bDst0 = smem0 + (A_BUF + lrow * LDSTR + lch) * 2;
    const __half* aSrc = g_xs + (size_t)(m0 + lrow) * KRED + lch;
    const __half* bSrc = g_wsT + (size_t)(n0 + lrow) * KRED + lch;

    // ldmatrix lane offsets
    const int aRow = (lane & 7) + ((lane >> 3) & 1) * 8;
    const int aK = (lane >> 4) * 8;
    const uint32_t aLdmOff = ((wm * 64 + aRow) * LDSTR + aK) * 2;
    const int bRow = (lane & 7) + ((lane >> 4) & 1) * 8;
    const int bK = ((lane >> 3) & 1) * 8;
    const uint32_t bLdmOff = (uint32_t)(A_BUF * 2) + ((wn * 64 + bRow) * LDSTR + bK) * 2;

    float acc[4][8][4];
#pragma unroll
    for (int mt = 0; mt < 4; mt++)
#pragma unroll
        for (int nt = 0; nt < 8; nt++)
#pragma unroll
            for (int i = 0; i < 4; i++) acc[mt][nt][i] = 0.f;

#pragma unroll
    for (int pc = 0; pc < 2; pc++) {
        const uint32_t so = pc * STAGE_B;
        const int kc = pc * KC;
#pragma unroll
        for (int r = 0; r < 8; r++) {
            cp16(aDst0 + so + r * 16 * LDSTR * 2, aSrc + (size_t)r * 16 * KRED + kc);
            cp16(bDst0 + so + r * 16 * LDSTR * 2, bSrc + (size_t)r * 16 * KRED + kc);
        }
        asm volatile("cp.async.commit_group;" ::: "memory");
    }

#pragma unroll
    for (int c = 0; c < 4; c++) {
        if (c < 3) asm volatile("cp.async.wait_group 1;" ::: "memory");
        else       asm volatile("cp.async.wait_group 0;" ::: "memory");
        __syncthreads();

        if (c < 2) {
            const int ns = (c + 2) % 3;
            const uint32_t so = ns * STAGE_B;
            const int kc = (c + 2) * KC;
#pragma unroll
            for (int r = 0; r < 8; r++) {
                cp16(aDst0 + so + r * 16 * LDSTR * 2, aSrc + (size_t)r * 16 * KRED + kc);
                cp16(bDst0 + so + r * 16 * LDSTR * 2, bSrc + (size_t)r * 16 * KRED + kc);
            }
            asm volatile("cp.async.commit_group;" ::: "memory");
        }

        const uint32_t stageBase = smem0 + (c % 3) * STAGE_B;
        const uint32_t aAddr = stageBase + aLdmOff;
        const uint32_t bAddr = stageBase + bLdmOff;

        // register double-buffered fragments over 4 k16 steps
        uint32_t a[2][4][4], b[2][8][2];
#pragma unroll
        for (int mt = 0; mt < 4; mt++)
            ldm_x4(a[0][mt][0], a[0][mt][1], a[0][mt][2], a[0][mt][3],
                   aAddr + mt * 16 * LDSTR * 2);
#pragma unroll
        for (int np = 0; np < 4; np++)
            ldm_x4(b[0][2 * np][0], b[0][2 * np][1],
                   b[0][2 * np + 1][0], b[0][2 * np + 1][1],
                   bAddr + np * 16 * LDSTR * 2);

#pragma unroll
        for (int s = 0; s < 4; s++) {
            const int cur = s & 1;
            if (s < 3) {
                const int nxt = cur ^ 1;
                const int kkB = (s + 1) * 16 * 2;
#pragma unroll
                for (int mt = 0; mt < 4; mt++)
                    ldm_x4(a[nxt][mt][0], a[nxt][mt][1], a[nxt][mt][2], a[nxt][mt][3],
                           aAddr + mt * 16 * LDSTR * 2 + kkB);
#pragma unroll
                for (int np = 0; np < 4; np++)
                    ldm_x4(b[nxt][2 * np][0], b[nxt][2 * np][1],
                           b[nxt][2 * np + 1][0], b[nxt][2 * np + 1][1],
                           bAddr + np * 16 * LDSTR * 2 + kkB);
            }
#pragma unroll
            for (int mt = 0; mt < 4; mt++)
#pragma unroll
                for (int nt = 0; nt < 8; nt++)
                    mma_f16(acc[mt][nt], a[cur][mt], b[cur][nt]);
        }
    }

    // Epilogue: bias + float2 stores
#pragma unroll
    for (int mt = 0; mt < 4; mt++) {
        const int r0 = m0 + wm * 64 + mt * 16 + g;
#pragma unroll
        for (int nt = 0; nt < 8; nt++) {
            const int col = wn * 64 + nt * 8 + 2 * t;
            const float b0 = s_bias[col], b1 = s_bias[col + 1];
            float2 v0 = make_float2(acc[mt][nt][0] + b0, acc[mt][nt][1] + b1);
            float2 v1 = make_float2(acc[mt][nt][2] + b0, acc[mt][nt][3] + b1);
            *(float2*)&out[(size_t)r0 * OUTF + n0 + col] = v0;
            *(float2*)&out[(size_t)(r0 + 8) * OUTF + n0 + col] = v1;
        }
    }
}

extern "C" void kernel_launch(void* const* d_in, const int* in_sizes, int n_in,
                              void* d_out, int out_size) {
    const float* x = (const float*)d_in[0];
    const float* w = (const float*)d_in[1];
    const float* bias = (const float*)d_in[2];
    float* out = (float*)d_out;

    cudaFuncSetAttribute(lin_gemm, cudaFuncAttributeMaxDynamicSharedMemorySize, SMEM_BYTES);

    lin_reduce<<<2048, 256>>>(x, w);
    dim3 grid(OUTF / BN, H / BM);   // (32, 32)
    lin_gemm<<<grid, 128, SMEM_BYTES>>>(bias, out);
}